// round 2
// baseline (speedup 1.0000x reference)
#include <cuda_runtime.h>

// SNN + STDP scan, 256 steps, 784 inputs, 512 neurons.
// Strategy: one warp owns one neuron. W row (784 f32) + pre-trace live in
// registers (float4[7] per lane, stride-32 chunk ownership, zero-padded).
// Only cross-thread op per step is a warp butterfly reduction for the GEMV.
// No __syncthreads in the main loop. x_{t+1} prefetched under the W update.

namespace {
constexpr int   T_STEPS = 256;
constexpr int   D_IN    = 784;
constexpr int   N_NEUR  = 512;
constexpr int   CHUNKS  = D_IN / 4;   // 196 float4 per row
constexpr int   KMAX    = 7;          // ceil(196/32) chunks per lane (padded)
constexpr float ALPHA      = 0.9f;    // synaptic decay
constexpr float BETA       = 0.8f;    // membrane decay
constexpr float THRESHOLD  = 1.0f;
constexpr float BETA_PLUS  = 0.9f;    // pre-trace decay
constexpr float BETA_MINUS = 0.9f;    // post-trace decay
constexpr float A_PLUS     = 0.008f;
constexpr float A_MINUS    = 0.0066f;
}

__global__ __launch_bounds__(128, 1)
void snn_persist(const float* __restrict__ image,
                 const float* __restrict__ W0,
                 float* __restrict__ out)
{
    const int lane = threadIdx.x & 31;
    const int warp = threadIdx.x >> 5;
    const int n    = (blockIdx.x << 2) + warp;   // neuron id, 0..511

    const float4 f4z = make_float4(0.f, 0.f, 0.f, 0.f);
    float4 w[KMAX], pre[KMAX], xc[KMAX], xn[KMAX];

    // Load this neuron's W row into registers (pad chunks -> 0, never stored).
    const float4* wrow = reinterpret_cast<const float4*>(W0) + (size_t)n * CHUNKS;
    #pragma unroll
    for (int k = 0; k < KMAX; ++k) {
        const int c = lane + 32 * k;
        w[k]   = (c < CHUNKS) ? __ldg(wrow + c) : f4z;
        pre[k] = f4z;
        xn[k]  = f4z;
    }
    // Prefetch x_0.
    {
        const float4* xrow = reinterpret_cast<const float4*>(image);
        #pragma unroll
        for (int k = 0; k < KMAX; ++k) {
            const int c = lane + 32 * k;
            xc[k] = (c < CHUNKS) ? __ldg(xrow + c) : f4z;
        }
    }

    float syn = 0.f, mem = 0.f, spk_prev = 0.f, post = 0.f;

    // Output layout: concatenated in reference return order.
    float* __restrict__ Wrec    = out;
    float* __restrict__ spkrec  = out + (size_t)T_STEPS * N_NEUR * D_IN;
    float* __restrict__ memrec  = spkrec  + T_STEPS * N_NEUR;
    float* __restrict__ synrec  = memrec  + T_STEPS * N_NEUR;
    float* __restrict__ postrec = synrec  + T_STEPS * N_NEUR;

    for (int t = 0; t < T_STEPS; ++t) {
        // ---- GEMV partial: I_n = sum_d W[n,d] * x_t[d] ----
        float4 a = f4z;
        #pragma unroll
        for (int k = 0; k < KMAX; ++k) {
            a.x = fmaf(w[k].x, xc[k].x, a.x);
            a.y = fmaf(w[k].y, xc[k].y, a.y);
            a.z = fmaf(w[k].z, xc[k].z, a.z);
            a.w = fmaf(w[k].w, xc[k].w, a.w);
        }
        float I = (a.x + a.y) + (a.z + a.w);
        // Butterfly allreduce: every lane ends with the full dot product,
        // so the scalar neuron update is replicated (no broadcast needed).
        #pragma unroll
        for (int s = 16; s > 0; s >>= 1)
            I += __shfl_xor_sync(0xffffffffu, I, s);

        // ---- prefetch x_{t+1} (latency hides under the W update below) ----
        if (t + 1 < T_STEPS) {
            const float4* xrow =
                reinterpret_cast<const float4*>(image) + (size_t)(t + 1) * CHUNKS;
            #pragma unroll
            for (int k = 0; k < KMAX; ++k) {
                const int c = lane + 32 * k;
                xn[k] = (c < CHUNKS) ? __ldg(xrow + c) : f4z;
            }
        }

        // ---- Synaptic LIF (subtract reset from previous spike) ----
        syn = fmaf(ALPHA, syn, I);
        mem = fmaf(BETA, mem, syn) - spk_prev * THRESHOLD;
        const float spk = (mem > THRESHOLD) ? 1.0f : 0.0f;
        post = fmaf(BETA_MINUS, post, spk);

        const float ap = A_PLUS * spk;        // LTP rate (0 when no spike)
        const float am = -(A_MINUS * post);   // negative LTD rate

        // ---- STDP weight update + clamp [0,1] + stream W_rec[t] ----
        float4* __restrict__ wdst =
            reinterpret_cast<float4*>(Wrec) + ((size_t)t * N_NEUR + n) * CHUNKS;
        #pragma unroll
        for (int k = 0; k < KMAX; ++k) {
            float4 wv = w[k];
            wv.x = __saturatef(fmaf(am, xc[k].x, fmaf(ap, pre[k].x, wv.x)));
            wv.y = __saturatef(fmaf(am, xc[k].y, fmaf(ap, pre[k].y, wv.y)));
            wv.z = __saturatef(fmaf(am, xc[k].z, fmaf(ap, pre[k].z, wv.z)));
            wv.w = __saturatef(fmaf(am, xc[k].w, fmaf(ap, pre[k].w, wv.w)));
            w[k] = wv;
            const int c = lane + 32 * k;
            if (c < CHUNKS) wdst[c] = wv;
            // pre-trace recurrence (uses x_t; old pre already consumed above)
            pre[k].x = fmaf(BETA_PLUS, pre[k].x, xc[k].x);
            pre[k].y = fmaf(BETA_PLUS, pre[k].y, xc[k].y);
            pre[k].z = fmaf(BETA_PLUS, pre[k].z, xc[k].z);
            pre[k].w = fmaf(BETA_PLUS, pre[k].w, xc[k].w);
        }

        // ---- scalar records (one lane per warp) ----
        if (lane == 0) {
            const int idx = t * N_NEUR + n;
            spkrec[idx]  = spk;
            memrec[idx]  = mem;
            synrec[idx]  = syn;
            postrec[idx] = post;
        }

        spk_prev = spk;
        #pragma unroll
        for (int k = 0; k < KMAX; ++k) xc[k] = xn[k];
    }
}

extern "C" void kernel_launch(void* const* d_in, const int* in_sizes, int n_in,
                              void* d_out, int out_size)
{
    const float* image = (const float*)d_in[0];  // [256, 784] f32
    const float* W     = (const float*)d_in[1];  // [512, 784] f32
    float* out = (float*)d_out;
    (void)in_sizes; (void)n_in; (void)out_size;
    snn_persist<<<N_NEUR / 4, 128>>>(image, W, out);
}

// round 3
// speedup vs baseline: 1.6567x; 1.6567x over previous
#include <cuda_runtime.h>

// SNN + STDP scan, 256 steps, 784 inputs, 512 neurons.
// R3 strategy: 4 warps cooperate on one neuron (2 float4 chunks per lane),
// 128 blocks x 512 threads -> 16 warps/SM, 4 warps/SMSP for latency hiding.
// Cross-warp GEMV reduce via double-buffered smem partials: exactly one
// __syncthreads per time step. Scalar LIF state is replicated per-thread
// (deterministic), so no broadcast is needed. W_rec stores use streaming
// hint (__stcs) to keep the 411MB write stream out of L2's way.

namespace {
constexpr int   T_STEPS = 256;
constexpr int   D_IN    = 784;
constexpr int   N_NEUR  = 512;
constexpr int   CHUNKS  = D_IN / 4;   // 196 float4 per row
constexpr int   WPN     = 4;          // warps per neuron
constexpr int   NPB     = 4;          // neurons per block
constexpr int   KMAX    = 2;          // chunks per lane (128-lane group, padded to 256)
constexpr float ALPHA      = 0.9f;
constexpr float BETA       = 0.8f;
constexpr float THRESHOLD  = 1.0f;
constexpr float BETA_PLUS  = 0.9f;
constexpr float BETA_MINUS = 0.9f;
constexpr float A_PLUS     = 0.008f;
constexpr float A_MINUS    = 0.0066f;
}

__global__ __launch_bounds__(512, 1)
void snn_persist4(const float* __restrict__ image,
                  const float* __restrict__ W0,
                  float* __restrict__ out)
{
    const int tid   = threadIdx.x;
    const int lane  = tid & 31;
    const int warp  = tid >> 5;          // 0..15
    const int group = warp >> 2;         // neuron slot in block, 0..3
    const int wing  = warp & 3;          // warp-in-neuron, 0..3
    const int n     = blockIdx.x * NPB + group;   // neuron id 0..511

    // chunk index for (k): c = wing*32 + lane + 128*k, k in {0,1}
    const int c0 = (wing << 5) + lane;

    const float4 f4z = make_float4(0.f, 0.f, 0.f, 0.f);
    float4 w[KMAX], pre[KMAX], xc[KMAX], xn[KMAX];

    const float4* wrow = reinterpret_cast<const float4*>(W0) + (size_t)n * CHUNKS;
    #pragma unroll
    for (int k = 0; k < KMAX; ++k) {
        const int c = c0 + (k << 7);
        w[k]   = (c < CHUNKS) ? __ldg(wrow + c) : f4z;
        pre[k] = f4z;
        xn[k]  = f4z;
    }
    {   // prefetch x_0
        const float4* xrow = reinterpret_cast<const float4*>(image);
        #pragma unroll
        for (int k = 0; k < KMAX; ++k) {
            const int c = c0 + (k << 7);
            xc[k] = (c < CHUNKS) ? __ldg(xrow + c) : f4z;
        }
    }

    // Double-buffered per-neuron warp partials (16B aligned for float4 read).
    __shared__ float4 part[2][NPB];

    float syn = 0.f, mem = 0.f, spk_prev = 0.f, post = 0.f;

    float* __restrict__ Wrec    = out;
    float* __restrict__ spkrec  = out + (size_t)T_STEPS * N_NEUR * D_IN;
    float* __restrict__ memrec  = spkrec  + T_STEPS * N_NEUR;
    float* __restrict__ synrec  = memrec  + T_STEPS * N_NEUR;
    float* __restrict__ postrec = synrec  + T_STEPS * N_NEUR;

    for (int t = 0; t < T_STEPS; ++t) {
        const int buf = t & 1;

        // ---- prefetch x_{t+1} early (latency hides under everything below) ----
        if (t + 1 < T_STEPS) {
            const float4* xrow =
                reinterpret_cast<const float4*>(image) + (size_t)(t + 1) * CHUNKS;
            #pragma unroll
            for (int k = 0; k < KMAX; ++k) {
                const int c = c0 + (k << 7);
                xn[k] = (c < CHUNKS) ? __ldg(xrow + c) : f4z;
            }
        }

        // ---- warp-partial GEMV: 8 FMAs + butterfly ----
        float4 a = f4z;
        #pragma unroll
        for (int k = 0; k < KMAX; ++k) {
            a.x = fmaf(w[k].x, xc[k].x, a.x);
            a.y = fmaf(w[k].y, xc[k].y, a.y);
            a.z = fmaf(w[k].z, xc[k].z, a.z);
            a.w = fmaf(w[k].w, xc[k].w, a.w);
        }
        float p = (a.x + a.y) + (a.z + a.w);
        #pragma unroll
        for (int s = 16; s > 0; s >>= 1)
            p += __shfl_xor_sync(0xffffffffu, p, s);

        if (lane == 0)
            reinterpret_cast<float*>(&part[buf][group])[wing] = p;
        __syncthreads();

        // ---- every thread reads the 4 partials and replicates the LIF update ----
        const float4 pv = part[buf][group];
        const float I = (pv.x + pv.y) + (pv.z + pv.w);

        syn = fmaf(ALPHA, syn, I);
        mem = fmaf(BETA, mem, syn) - spk_prev * THRESHOLD;
        const float spk = (mem > THRESHOLD) ? 1.0f : 0.0f;
        post = fmaf(BETA_MINUS, post, spk);

        const float ap = A_PLUS * spk;
        const float am = -(A_MINUS * post);

        // ---- STDP weight update + clamp + streaming store of W_rec[t] ----
        float4* __restrict__ wdst =
            reinterpret_cast<float4*>(Wrec) + ((size_t)t * N_NEUR + n) * CHUNKS;
        #pragma unroll
        for (int k = 0; k < KMAX; ++k) {
            float4 wv = w[k];
            wv.x = __saturatef(fmaf(am, xc[k].x, fmaf(ap, pre[k].x, wv.x)));
            wv.y = __saturatef(fmaf(am, xc[k].y, fmaf(ap, pre[k].y, wv.y)));
            wv.z = __saturatef(fmaf(am, xc[k].z, fmaf(ap, pre[k].z, wv.z)));
            wv.w = __saturatef(fmaf(am, xc[k].w, fmaf(ap, pre[k].w, wv.w)));
            w[k] = wv;
            const int c = c0 + (k << 7);
            if (c < CHUNKS) __stcs(wdst + c, wv);
            pre[k].x = fmaf(BETA_PLUS, pre[k].x, xc[k].x);
            pre[k].y = fmaf(BETA_PLUS, pre[k].y, xc[k].y);
            pre[k].z = fmaf(BETA_PLUS, pre[k].z, xc[k].z);
            pre[k].w = fmaf(BETA_PLUS, pre[k].w, xc[k].w);
        }

        // ---- scalar records: one thread per neuron ----
        if (wing == 0 && lane == 0) {
            const int idx = t * N_NEUR + n;
            spkrec[idx]  = spk;
            memrec[idx]  = mem;
            synrec[idx]  = syn;
            postrec[idx] = post;
        }

        spk_prev = spk;
        #pragma unroll
        for (int k = 0; k < KMAX; ++k) xc[k] = xn[k];
    }
}

extern "C" void kernel_launch(void* const* d_in, const int* in_sizes, int n_in,
                              void* d_out, int out_size)
{
    const float* image = (const float*)d_in[0];  // [256, 784] f32
    const float* W     = (const float*)d_in[1];  // [512, 784] f32
    float* out = (float*)d_out;
    (void)in_sizes; (void)n_in; (void)out_size;
    snn_persist4<<<N_NEUR / NPB, NPB * WPN * 32>>>(image, W, out);
}

// round 6
// speedup vs baseline: 1.7763x; 1.0722x over previous
#include <cuda_runtime.h>

// SNN + STDP scan, 256 steps, 784 inputs, 512 neurons.
// R5: 4 warps per neuron, 4 neurons per 512-thread block, 128 blocks.
// - Next-step GEMV fused into the W-update loop (a_next += wv * x_{t+1}).
// - Warp reduce shortened to 3 shfl steps -> 4 per-8-lane partials stored to
//   smem (16 floats/neuron); every thread sums 16 after the barrier.
//   (redux.sync.add.f32 does NOT exist on sm_103a - ptxas rejects it.)
// - Per-neuron named barrier (bar.sync id,128), not block-wide __syncthreads.
// - W_rec written with streaming hint (__stcs): 411 MB write-once stream.

namespace {
constexpr int   T_STEPS = 256;
constexpr int   D_IN    = 784;
constexpr int   N_NEUR  = 512;
constexpr int   CHUNKS  = D_IN / 4;   // 196 float4 per row
constexpr int   WPN     = 4;          // warps per neuron
constexpr int   NPB     = 4;          // neurons per block
constexpr int   KMAX    = 2;          // float4 chunks per lane (padded 196->256)
constexpr float ALPHA      = 0.9f;
constexpr float BETA       = 0.8f;
constexpr float THRESHOLD  = 1.0f;
constexpr float BETA_PLUS  = 0.9f;
constexpr float BETA_MINUS = 0.9f;
constexpr float A_PLUS     = 0.008f;
constexpr float A_MINUS    = 0.0066f;
}

__device__ __forceinline__ void neuron_bar(int id) {
    asm volatile("bar.sync %0, 128;" :: "r"(id) : "memory");
}

__global__ __launch_bounds__(512, 1)
void snn_fused(const float* __restrict__ image,
               const float* __restrict__ W0,
               float* __restrict__ out)
{
    const int tid   = threadIdx.x;
    const int lane  = tid & 31;
    const int warp  = tid >> 5;          // 0..15
    const int group = warp >> 2;         // neuron slot in block, 0..3
    const int wing  = warp & 3;          // warp-in-neuron, 0..3
    const int n     = blockIdx.x * NPB + group;
    const int barid = group + 1;         // named barrier ids 1..4

    const int c0 = (wing << 5) + lane;   // chunk = c0 + 128*k

    const float4 f4z = make_float4(0.f, 0.f, 0.f, 0.f);
    float4 w[KMAX], pre[KMAX], xc[KMAX], xn[KMAX], a;

    const float4* wrow = reinterpret_cast<const float4*>(W0) + (size_t)n * CHUNKS;
    #pragma unroll
    for (int k = 0; k < KMAX; ++k) {
        const int c = c0 + (k << 7);
        w[k]   = (c < CHUNKS) ? __ldg(wrow + c) : f4z;
        pre[k] = f4z;
    }
    {   // prefetch x_0, x_1
        const float4* xrow = reinterpret_cast<const float4*>(image);
        #pragma unroll
        for (int k = 0; k < KMAX; ++k) {
            const int c = c0 + (k << 7);
            xc[k] = (c < CHUNKS) ? __ldg(xrow + c) : f4z;
            xn[k] = (c < CHUNKS) ? __ldg(xrow + CHUNKS + c) : f4z;
        }
    }

    // Prologue dot: a = per-lane partial of W0 . x_0
    a = f4z;
    #pragma unroll
    for (int k = 0; k < KMAX; ++k) {
        a.x = fmaf(w[k].x, xc[k].x, a.x);
        a.y = fmaf(w[k].y, xc[k].y, a.y);
        a.z = fmaf(w[k].z, xc[k].z, a.z);
        a.w = fmaf(w[k].w, xc[k].w, a.w);
    }

    // Per-neuron partials: 4 wings x 4 eighth-partials, double buffered.
    __shared__ float4 part[2][NPB][WPN];

    float syn = 0.f, mem = 0.f, spk_prev = 0.f, post = 0.f;

    float* __restrict__ Wrec    = out;
    float* __restrict__ spkrec  = out + (size_t)T_STEPS * N_NEUR * D_IN;
    float* __restrict__ memrec  = spkrec  + T_STEPS * N_NEUR;
    float* __restrict__ synrec  = memrec  + T_STEPS * N_NEUR;
    float* __restrict__ postrec = synrec  + T_STEPS * N_NEUR;

    for (int t = 0; t < T_STEPS; ++t) {
        const int buf = t & 1;

        // ---- partial reduce: 3 shfl steps -> per-8-lane sums on lanes 0,8,16,24
        float p = (a.x + a.y) + (a.z + a.w);
        p += __shfl_xor_sync(0xffffffffu, p, 1);
        p += __shfl_xor_sync(0xffffffffu, p, 2);
        p += __shfl_xor_sync(0xffffffffu, p, 4);
        if ((lane & 7) == 0)
            reinterpret_cast<float*>(&part[buf][group][wing])[lane >> 3] = p;
        neuron_bar(barid);

        // ---- every thread sums the 16 partials (4 x LDS.128, pipelined) ----
        float I;
        {
            const float4 q0 = part[buf][group][0];
            const float4 q1 = part[buf][group][1];
            const float4 q2 = part[buf][group][2];
            const float4 q3 = part[buf][group][3];
            const float s0 = (q0.x + q0.y) + (q0.z + q0.w);
            const float s1 = (q1.x + q1.y) + (q1.z + q1.w);
            const float s2 = (q2.x + q2.y) + (q2.z + q2.w);
            const float s3 = (q3.x + q3.y) + (q3.z + q3.w);
            I = (s0 + s1) + (s2 + s3);
        }

        // ---- Synaptic LIF (replicated deterministically across 128 threads) ----
        syn = fmaf(ALPHA, syn, I);
        mem = fmaf(BETA, mem, syn) - spk_prev * THRESHOLD;
        const float spk = (mem > THRESHOLD) ? 1.0f : 0.0f;
        post = fmaf(BETA_MINUS, post, spk);

        const float ap = A_PLUS * spk;
        const float am = -(A_MINUS * post);

        // ---- STDP update + clamp + store W_rec[t]; fuse next GEMV ----
        float4 an = f4z;
        float4* __restrict__ wdst =
            reinterpret_cast<float4*>(Wrec) + ((size_t)t * N_NEUR + n) * CHUNKS;
        #pragma unroll
        for (int k = 0; k < KMAX; ++k) {
            float4 wv = w[k];
            wv.x = __saturatef(fmaf(am, xc[k].x, fmaf(ap, pre[k].x, wv.x)));
            wv.y = __saturatef(fmaf(am, xc[k].y, fmaf(ap, pre[k].y, wv.y)));
            wv.z = __saturatef(fmaf(am, xc[k].z, fmaf(ap, pre[k].z, wv.z)));
            wv.w = __saturatef(fmaf(am, xc[k].w, fmaf(ap, pre[k].w, wv.w)));
            w[k] = wv;
            const int c = c0 + (k << 7);
            if (c < CHUNKS) __stcs(wdst + c, wv);
            // fused dot for step t+1: W(t) . x_{t+1}
            an.x = fmaf(wv.x, xn[k].x, an.x);
            an.y = fmaf(wv.y, xn[k].y, an.y);
            an.z = fmaf(wv.z, xn[k].z, an.z);
            an.w = fmaf(wv.w, xn[k].w, an.w);
            // pre-trace recurrence uses x_t
            pre[k].x = fmaf(BETA_PLUS, pre[k].x, xc[k].x);
            pre[k].y = fmaf(BETA_PLUS, pre[k].y, xc[k].y);
            pre[k].z = fmaf(BETA_PLUS, pre[k].z, xc[k].z);
            pre[k].w = fmaf(BETA_PLUS, pre[k].w, xc[k].w);
        }
        a = an;

        // ---- scalar records (one thread per neuron) ----
        if (wing == 0 && lane == 0) {
            const int idx = t * N_NEUR + n;
            spkrec[idx]  = spk;
            memrec[idx]  = mem;
            synrec[idx]  = syn;
            postrec[idx] = post;
        }

        spk_prev = spk;

        // ---- rotate x buffers; prefetch x_{t+2} (overlaps next barrier) ----
        #pragma unroll
        for (int k = 0; k < KMAX; ++k) xc[k] = xn[k];
        if (t + 2 < T_STEPS) {
            const float4* xrow =
                reinterpret_cast<const float4*>(image) + (size_t)(t + 2) * CHUNKS;
            #pragma unroll
            for (int k = 0; k < KMAX; ++k) {
                const int c = c0 + (k << 7);
                if (c < CHUNKS) xn[k] = __ldg(xrow + c);
            }
        }
    }
}

extern "C" void kernel_launch(void* const* d_in, const int* in_sizes, int n_in,
                              void* d_out, int out_size)
{
    const float* image = (const float*)d_in[0];  // [256, 784] f32
    const float* W     = (const float*)d_in[1];  // [512, 784] f32
    float* out = (float*)d_out;
    (void)in_sizes; (void)n_in; (void)out_size;
    snn_fused<<<N_NEUR / NPB, NPB * WPN * 32>>>(image, W, out);
}

// round 7
// speedup vs baseline: 1.9747x; 1.1117x over previous
#include <cuda_runtime.h>

// SNN + STDP scan, 256 steps, 784 inputs, 512 neurons.
// R6: same 4-warps/neuron structure as R5, minus issue slots:
//  - packed fma.rn.f32x2 for LTP term, pre-trace update, fused next-step dot
//    (saturating LTD FMA stays scalar FFMA.SAT; .sat on f32x2 unverified)
//  - full 5-shfl butterfly -> lane0 stores ONE float; post-barrier I is one
//    broadcast LDS.128 + 3 FADD
//  - #pragma unroll 2 on t-loop (x ping-pong renamed away), incremental ptrs
//  - per-neuron named barrier, __stcs streaming stores for the 411MB W_rec

namespace {
constexpr int   T_STEPS = 256;
constexpr int   D_IN    = 784;
constexpr int   N_NEUR  = 512;
constexpr int   CHUNKS  = D_IN / 4;   // 196 float4 per row
constexpr int   WPN     = 4;
constexpr int   NPB     = 4;
constexpr int   KMAX    = 2;          // float4 chunks per lane (padded 196->256)
constexpr float ALPHA      = 0.9f;
constexpr float BETA       = 0.8f;
constexpr float THRESHOLD  = 1.0f;
constexpr float BETA_PLUS  = 0.9f;
constexpr float BETA_MINUS = 0.9f;
constexpr float A_PLUS     = 0.008f;
constexpr float A_MINUS    = 0.0066f;
}

using u64 = unsigned long long;

__device__ __forceinline__ u64 pk2(float lo, float hi) {
    u64 r; asm("mov.b64 %0, {%1, %2};" : "=l"(r) : "f"(lo), "f"(hi)); return r;
}
__device__ __forceinline__ void upk2(u64 v, float& lo, float& hi) {
    asm("mov.b64 {%0, %1}, %2;" : "=f"(lo), "=f"(hi) : "l"(v));
}
// Two independent fma.rn.f32 in one instruction (FFMA2).
__device__ __forceinline__ u64 ffma2(u64 a, u64 b, u64 c) {
    u64 d; asm("fma.rn.f32x2 %0, %1, %2, %3;" : "=l"(d) : "l"(a), "l"(b), "l"(c));
    return d;
}
__device__ __forceinline__ void neuron_bar(int id) {
    asm volatile("bar.sync %0, 128;" :: "r"(id) : "memory");
}

__global__ __launch_bounds__(512, 1)
void snn_fused2(const float* __restrict__ image,
                const float* __restrict__ W0,
                float* __restrict__ out)
{
    const int tid   = threadIdx.x;
    const int lane  = tid & 31;
    const int warp  = tid >> 5;          // 0..15
    const int group = warp >> 2;         // neuron slot, 0..3
    const int wing  = warp & 3;          // warp-in-neuron (== SMSP id)
    const int n     = blockIdx.x * NPB + group;
    const int barid = group + 1;

    const int  c0  = (wing << 5) + lane; // k=0 chunk, always < 128 < CHUNKS
    const int  c1  = c0 + 128;           // k=1 chunk
    const bool k1v = (c1 < CHUNKS);

    const float4 f4z = make_float4(0.f, 0.f, 0.f, 0.f);

    u64 w01[KMAX], w23[KMAX], pre01[KMAX], pre23[KMAX];
    float4 xc[KMAX], xn[KMAX];

    // ---- load W row (packed), init traces, prefetch x_0 / x_1 ----
    {
        const float4* wrow = reinterpret_cast<const float4*>(W0) + (size_t)n * CHUNKS;
        float4 t0 = __ldg(wrow + c0);
        float4 t1 = k1v ? __ldg(wrow + c1) : f4z;
        w01[0] = pk2(t0.x, t0.y);  w23[0] = pk2(t0.z, t0.w);
        w01[1] = pk2(t1.x, t1.y);  w23[1] = pk2(t1.z, t1.w);
    }
    #pragma unroll
    for (int k = 0; k < KMAX; ++k) { pre01[k] = 0ull; pre23[k] = 0ull; }

    const float4* xrow = reinterpret_cast<const float4*>(image);
    xc[0] = __ldg(xrow + c0);
    xc[1] = k1v ? __ldg(xrow + c1) : f4z;
    xn[0] = __ldg(xrow + CHUNKS + c0);
    xn[1] = k1v ? __ldg(xrow + CHUNKS + c1) : f4z;
    const float4* xpf = xrow + 2 * (size_t)CHUNKS;   // source of x_{t+2}

    // ---- prologue dot: a = per-lane packed partials of W0 . x_0 ----
    u64 a01, a23;
    a01 = ffma2(w01[0], pk2(xc[0].x, xc[0].y), 0ull);
    a01 = ffma2(w01[1], pk2(xc[1].x, xc[1].y), a01);
    a23 = ffma2(w23[0], pk2(xc[0].z, xc[0].w), 0ull);
    a23 = ffma2(w23[1], pk2(xc[1].z, xc[1].w), a23);

    __shared__ float4 part4[2][NPB];   // 4 wing totals per neuron, double buffered

    float syn = 0.f, mem = 0.f, spk_prev = 0.f, post = 0.f;
    const u64 bp2 = pk2(BETA_PLUS, BETA_PLUS);

    float* __restrict__ spkrec  = out + (size_t)T_STEPS * N_NEUR * D_IN;
    float* __restrict__ memrec  = spkrec  + T_STEPS * N_NEUR;
    float* __restrict__ synrec  = memrec  + T_STEPS * N_NEUR;
    float* __restrict__ postrec = synrec  + T_STEPS * N_NEUR;

    float4* wptr = reinterpret_cast<float4*>(out) + (size_t)n * CHUNKS;
    int sidx = n;

    #pragma unroll 2
    for (int t = 0; t < T_STEPS; ++t) {
        const int buf = t & 1;

        // ---- wing total: 5-step butterfly, lane0 stores ONE float ----
        float aw, ax, ay, az;
        upk2(a01, aw, ax);
        upk2(a23, ay, az);
        float p = (aw + ax) + (ay + az);
        #pragma unroll
        for (int s = 1; s < 32; s <<= 1)
            p += __shfl_xor_sync(0xffffffffu, p, s);
        if (lane == 0)
            reinterpret_cast<float*>(&part4[buf][group])[wing] = p;
        neuron_bar(barid);

        // ---- I: one broadcast LDS.128 + 3 adds ----
        const float4 q = part4[buf][group];
        const float I = (q.x + q.y) + (q.z + q.w);

        // ---- Synaptic LIF (replicated deterministically) ----
        syn = fmaf(ALPHA, syn, I);
        mem = fmaf(BETA, mem, syn) - spk_prev * THRESHOLD;
        const float spk = (mem > THRESHOLD) ? 1.0f : 0.0f;
        post = fmaf(BETA_MINUS, post, spk);

        const float ap  = A_PLUS * spk;
        const float am  = -(A_MINUS * post);
        const u64   ap2 = pk2(ap, ap);

        // ---- STDP update + store W_rec[t] + fused next dot ----
        a01 = 0ull; a23 = 0ull;
        #pragma unroll
        for (int k = 0; k < KMAX; ++k) {
            const bool act = (k == 0) || k1v;
            const int  c   = (k == 0) ? c0 : c1;

            // LTP half: t = ap*pre + w   (packed, 2 FFMA2)
            u64 t01 = ffma2(ap2, pre01[k], w01[k]);
            u64 t23 = ffma2(ap2, pre23[k], w23[k]);
            float tx, ty, tz, tw;
            upk2(t01, tx, ty);
            upk2(t23, tz, tw);

            const float4 xck = xc[k];
            float4 wv;
            wv.x = __saturatef(fmaf(am, xck.x, tx));
            wv.y = __saturatef(fmaf(am, xck.y, ty));
            wv.z = __saturatef(fmaf(am, xck.z, tz));
            wv.w = __saturatef(fmaf(am, xck.w, tw));
            if (act) __stcs(wptr + c, wv);

            const u64 wp01 = pk2(wv.x, wv.y);
            const u64 wp23 = pk2(wv.z, wv.w);
            w01[k] = wp01;
            w23[k] = wp23;

            // pre-trace recurrence (packed), last use of xc[k]
            pre01[k] = ffma2(bp2, pre01[k], pk2(xck.x, xck.y));
            pre23[k] = ffma2(bp2, pre23[k], pk2(xck.z, xck.w));

            // fused dot for step t+1: W(t) . x_{t+1}  (packed)
            const float4 xnk = xn[k];
            a01 = ffma2(wp01, pk2(xnk.x, xnk.y), a01);
            a23 = ffma2(wp23, pk2(xnk.z, xnk.w), a23);

            // rotate + prefetch x_{t+2} (copies renamed away by unroll-2)
            xc[k] = xnk;
            if (act && (t + 2 < T_STEPS)) xn[k] = __ldg(xpf + c);
        }

        // ---- scalar records (one thread per neuron) ----
        if (wing == 0 && lane == 0) {
            spkrec[sidx]  = spk;
            memrec[sidx]  = mem;
            synrec[sidx]  = syn;
            postrec[sidx] = post;
        }

        spk_prev = spk;
        wptr += (size_t)N_NEUR * CHUNKS;
        xpf  += CHUNKS;
        sidx += N_NEUR;
    }
}

extern "C" void kernel_launch(void* const* d_in, const int* in_sizes, int n_in,
                              void* d_out, int out_size)
{
    const float* image = (const float*)d_in[0];  // [256, 784] f32
    const float* W     = (const float*)d_in[1];  // [512, 784] f32
    float* out = (float*)d_out;
    (void)in_sizes; (void)n_in; (void)out_size;
    snn_fused2<<<N_NEUR / NPB, NPB * WPN * 32>>>(image, W, out);
}

// round 8
// speedup vs baseline: 1.9826x; 1.0040x over previous
#include <cuda_runtime.h>

// SNN + STDP scan, 256 steps, 784 inputs, 512 neurons.
// R7 = R6 (packed f32x2 math, 5-shfl butterfly + 1-float partial, per-neuron
// named barrier, __stcs streaming W_rec stores) + PHASE SKEW:
// the 4 neuron-groups of a block are identical and never inter-sync, so their
// warps run in lockstep on each SMSP -> all 4 warps stall in the shfl/barrier
// chain simultaneously (measured issue=26%). A one-time group-proportional
// dummy delay (~1/4 step per group) de-phases them permanently, letting one
// group's dependent-latency phase overlap another's issue phase.

namespace {
constexpr int   T_STEPS = 256;
constexpr int   D_IN    = 784;
constexpr int   N_NEUR  = 512;
constexpr int   CHUNKS  = D_IN / 4;   // 196 float4 per row
constexpr int   WPN     = 4;
constexpr int   NPB     = 4;
constexpr int   KMAX    = 2;
constexpr float ALPHA      = 0.9f;
constexpr float BETA       = 0.8f;
constexpr float THRESHOLD  = 1.0f;
constexpr float BETA_PLUS  = 0.9f;
constexpr float BETA_MINUS = 0.9f;
constexpr float A_PLUS     = 0.008f;
constexpr float A_MINUS    = 0.0066f;
constexpr int   SKEW_ITERS = 24;      // dependent FFMAs per group step (~1/4 loop period)
}

using u64 = unsigned long long;

__device__ __forceinline__ u64 pk2(float lo, float hi) {
    u64 r; asm("mov.b64 %0, {%1, %2};" : "=l"(r) : "f"(lo), "f"(hi)); return r;
}
__device__ __forceinline__ void upk2(u64 v, float& lo, float& hi) {
    asm("mov.b64 {%0, %1}, %2;" : "=f"(lo), "=f"(hi) : "l"(v));
}
__device__ __forceinline__ u64 ffma2(u64 a, u64 b, u64 c) {
    u64 d; asm("fma.rn.f32x2 %0, %1, %2, %3;" : "=l"(d) : "l"(a), "l"(b), "l"(c));
    return d;
}
__device__ __forceinline__ void neuron_bar(int id) {
    asm volatile("bar.sync %0, 128;" :: "r"(id) : "memory");
}

__global__ __launch_bounds__(512, 1)
void snn_fused3(const float* __restrict__ image,
                const float* __restrict__ W0,
                float* __restrict__ out)
{
    const int tid   = threadIdx.x;
    const int lane  = tid & 31;
    const int warp  = tid >> 5;
    const int group = warp >> 2;         // neuron slot, 0..3
    const int wing  = warp & 3;          // warp-in-neuron (== SMSP id)
    const int n     = blockIdx.x * NPB + group;
    const int barid = group + 1;

    const int  c0  = (wing << 5) + lane;
    const int  c1  = c0 + 128;
    const bool k1v = (c1 < CHUNKS);

    const float4 f4z = make_float4(0.f, 0.f, 0.f, 0.f);

    u64 w01[KMAX], w23[KMAX], pre01[KMAX], pre23[KMAX];
    float4 xc[KMAX], xn[KMAX];

    {   // load W row (packed)
        const float4* wrow = reinterpret_cast<const float4*>(W0) + (size_t)n * CHUNKS;
        float4 t0 = __ldg(wrow + c0);
        float4 t1 = k1v ? __ldg(wrow + c1) : f4z;
        w01[0] = pk2(t0.x, t0.y);  w23[0] = pk2(t0.z, t0.w);
        w01[1] = pk2(t1.x, t1.y);  w23[1] = pk2(t1.z, t1.w);
    }
    #pragma unroll
    for (int k = 0; k < KMAX; ++k) { pre01[k] = 0ull; pre23[k] = 0ull; }

    const float4* xrow = reinterpret_cast<const float4*>(image);
    xc[0] = __ldg(xrow + c0);
    xc[1] = k1v ? __ldg(xrow + c1) : f4z;
    xn[0] = __ldg(xrow + CHUNKS + c0);
    xn[1] = k1v ? __ldg(xrow + CHUNKS + c1) : f4z;
    const float4* xpf = xrow + 2 * (size_t)CHUNKS;

    // ---- one-time phase skew: ~SKEW_ITERS*4 cyc per group index ----
    // Dead value; asm volatile keeps the dependent chain. No output effect.
    {
        float d = 1.0f;
        const int iters = group * SKEW_ITERS;
        #pragma unroll 1
        for (int i = 0; i < iters; ++i)
            asm volatile("fma.rn.f32 %0, %0, 0f3F800001, 0f00000000;" : "+f"(d));
    }

    // ---- prologue dot: W0 . x_0 ----
    u64 a01, a23;
    a01 = ffma2(w01[0], pk2(xc[0].x, xc[0].y), 0ull);
    a01 = ffma2(w01[1], pk2(xc[1].x, xc[1].y), a01);
    a23 = ffma2(w23[0], pk2(xc[0].z, xc[0].w), 0ull);
    a23 = ffma2(w23[1], pk2(xc[1].z, xc[1].w), a23);

    __shared__ float4 part4[2][NPB];

    float syn = 0.f, mem = 0.f, spk_prev = 0.f, post = 0.f;
    const u64 bp2 = pk2(BETA_PLUS, BETA_PLUS);

    float* __restrict__ spkrec  = out + (size_t)T_STEPS * N_NEUR * D_IN;
    float* __restrict__ memrec  = spkrec  + T_STEPS * N_NEUR;
    float* __restrict__ synrec  = memrec  + T_STEPS * N_NEUR;
    float* __restrict__ postrec = synrec  + T_STEPS * N_NEUR;

    float4* wptr = reinterpret_cast<float4*>(out) + (size_t)n * CHUNKS;
    int sidx = n;

    #pragma unroll 2
    for (int t = 0; t < T_STEPS; ++t) {
        const int buf = t & 1;

        // ---- wing total: 5-step butterfly, lane0 stores one float ----
        float aw, ax, ay, az;
        upk2(a01, aw, ax);
        upk2(a23, ay, az);
        float p = (aw + ax) + (ay + az);
        #pragma unroll
        for (int s = 1; s < 32; s <<= 1)
            p += __shfl_xor_sync(0xffffffffu, p, s);
        if (lane == 0)
            reinterpret_cast<float*>(&part4[buf][group])[wing] = p;
        neuron_bar(barid);

        // ---- I: one broadcast LDS.128 + 3 adds ----
        const float4 q = part4[buf][group];
        const float I = (q.x + q.y) + (q.z + q.w);

        // ---- Synaptic LIF (replicated deterministically) ----
        syn = fmaf(ALPHA, syn, I);
        mem = fmaf(BETA, mem, syn) - spk_prev * THRESHOLD;
        const float spk = (mem > THRESHOLD) ? 1.0f : 0.0f;
        post = fmaf(BETA_MINUS, post, spk);

        const float ap  = A_PLUS * spk;
        const float am  = -(A_MINUS * post);
        const u64   ap2 = pk2(ap, ap);

        // ---- STDP update + store W_rec[t] + fused next dot ----
        a01 = 0ull; a23 = 0ull;
        #pragma unroll
        for (int k = 0; k < KMAX; ++k) {
            const bool act = (k == 0) || k1v;
            const int  c   = (k == 0) ? c0 : c1;

            u64 t01 = ffma2(ap2, pre01[k], w01[k]);
            u64 t23 = ffma2(ap2, pre23[k], w23[k]);
            float tx, ty, tz, tw;
            upk2(t01, tx, ty);
            upk2(t23, tz, tw);

            const float4 xck = xc[k];
            float4 wv;
            wv.x = __saturatef(fmaf(am, xck.x, tx));
            wv.y = __saturatef(fmaf(am, xck.y, ty));
            wv.z = __saturatef(fmaf(am, xck.z, tz));
            wv.w = __saturatef(fmaf(am, xck.w, tw));
            if (act) __stcs(wptr + c, wv);

            const u64 wp01 = pk2(wv.x, wv.y);
            const u64 wp23 = pk2(wv.z, wv.w);
            w01[k] = wp01;
            w23[k] = wp23;

            pre01[k] = ffma2(bp2, pre01[k], pk2(xck.x, xck.y));
            pre23[k] = ffma2(bp2, pre23[k], pk2(xck.z, xck.w));

            const float4 xnk = xn[k];
            a01 = ffma2(wp01, pk2(xnk.x, xnk.y), a01);
            a23 = ffma2(wp23, pk2(xnk.z, xnk.w), a23);

            xc[k] = xnk;
            if (act && (t + 2 < T_STEPS)) xn[k] = __ldg(xpf + c);
        }

        // ---- scalar records (one thread per neuron) ----
        if (wing == 0 && lane == 0) {
            spkrec[sidx]  = spk;
            memrec[sidx]  = mem;
            synrec[sidx]  = syn;
            postrec[sidx] = post;
        }

        spk_prev = spk;
        wptr += (size_t)N_NEUR * CHUNKS;
        xpf  += CHUNKS;
        sidx += N_NEUR;
    }
}

extern "C" void kernel_launch(void* const* d_in, const int* in_sizes, int n_in,
                              void* d_out, int out_size)
{
    const float* image = (const float*)d_in[0];  // [256, 784] f32
    const float* W     = (const float*)d_in[1];  // [512, 784] f32
    float* out = (float*)d_out;
    (void)in_sizes; (void)n_in; (void)out_size;
    snn_fused3<<<N_NEUR / NPB, NPB * WPN * 32>>>(image, W, out);
}